// round 16
// baseline (speedup 1.0000x reference)
#include <cuda_runtime.h>
#include <cuda_fp16.h>
#include <math.h>

#define BB 8
#define NHEADS 16
#define DH 48
#define DD 768
#define P2 256

typedef unsigned long long ull;

// ---- f32x2 packed helpers (conv) ----
__device__ __forceinline__ ull pk2(float lo, float hi) {
    ull r; asm("mov.b64 %0,{%1,%2};" : "=l"(r) : "f"(lo), "f"(hi)); return r;
}
__device__ __forceinline__ ull dup2(float v) {
    ull r; asm("mov.b64 %0,{%1,%1};" : "=l"(r) : "f"(v)); return r;
}
__device__ __forceinline__ void fma2(ull& d, ull a, ull b) {
    asm("fma.rn.f32x2 %0,%1,%2,%0;" : "+l"(d) : "l"(a), "l"(b));
}
__device__ __forceinline__ float2 up2(ull v) {
    float2 r; asm("mov.b64 {%0,%1},%2;" : "=f"(r.x), "=f"(r.y) : "l"(v)); return r;
}

// ---- tensor-core helpers ----
__device__ __forceinline__ uint4 ldsm4(unsigned a) {
    uint4 r;
    asm volatile("ldmatrix.sync.aligned.m8n8.x4.shared.b16 {%0,%1,%2,%3},[%4];"
                 : "=r"(r.x), "=r"(r.y), "=r"(r.z), "=r"(r.w) : "r"(a));
    return r;
}
__device__ __forceinline__ uint4 ldsm4t(unsigned a) {
    uint4 r;
    asm volatile("ldmatrix.sync.aligned.m8n8.x4.trans.shared.b16 {%0,%1,%2,%3},[%4];"
                 : "=r"(r.x), "=r"(r.y), "=r"(r.z), "=r"(r.w) : "r"(a));
    return r;
}
__device__ __forceinline__ void mma16816(float d[4], const uint4& a, const uint2& b) {
    asm volatile("mma.sync.aligned.m16n8k16.row.col.f32.f16.f16.f32 "
                 "{%0,%1,%2,%3},{%4,%5,%6,%7},{%8,%9},{%0,%1,%2,%3};"
                 : "+f"(d[0]), "+f"(d[1]), "+f"(d[2]), "+f"(d[3])
                 : "r"(a.x), "r"(a.y), "r"(a.z), "r"(a.w), "r"(b.x), "r"(b.y));
}

// Scratch: windowified Q/K/V all fp16  [b][head][n][pix4][dh], 128B aligned
__device__ __align__(128) __half g_Qh[BB*NHEADS*P2*4*DH];
__device__ __align__(128) __half g_Kh[BB*NHEADS*P2*4*DH];
__device__ __align__(128) __half g_Vh[BB*NHEADS*P2*4*DH];
// Packed top-8 selections per window (8 x u8 in a u64)
__device__ ull g_sel[BB*NHEADS*P2];

// ---------------------------------------------------------------------------
// Block-specialized kernel: 1536 conv blocks (every 6th bid, interleaved with)
// 8192 topk blocks. Conv is latency-bound (idle issue slots); topk is
// ALU/issue-bound with no memory pressure — they share SM issue bandwidth.
// ---------------------------------------------------------------------------
__global__ __launch_bounds__(128) void convtopk_kernel(const float* __restrict__ x,
                                                       const float* __restrict__ conv_w,
                                                       const float* __restrict__ gamma,
                                                       const float* __restrict__ beta,
                                                       const float* __restrict__ mean,
                                                       const float* __restrict__ var,
                                                       const float* __restrict__ adj) {
    __shared__ ull  wdup[3][25][32];
    __shared__ ull  bdup[3][32];
    __shared__ float sinv[3][32];

    int bid = blockIdx.x;
    bool isconv = ((bid % 6) == 0) && (bid / 6 < 1536);

    if (isconv) {
        // ================= conv path (R12, best measured) =================
        int cid   = bid / 6;
        int b     = cid / 192;
        int gx    = cid - b * 192;
        int chunk = gx >> 3;
        int rpair = gx & 7;           // 4-row band
        int tid   = threadIdx.x;
        int lane5 = tid & 31;
        int slot  = tid >> 5;         // 0..3 -> col group
        int c0    = chunk * 32;
        int c     = c0 + lane5;

        if (tid < 96) {
            int j  = tid / 32;
            int cl = tid % 32;
            int t  = j * DD + c0 + cl;
            float inv = gamma[t] * rsqrtf(var[t] + 1e-5f);
            float bs  = beta[t] - mean[t] * inv;
            if (j == 0) { inv *= 0.03608439182435161f; bs *= 0.03608439182435161f; }
            sinv[j][cl] = inv;
            bdup[j][cl] = dup2(bs);
        }
        __syncthreads();
        for (int f = tid; f < 3 * 800; f += 128) {
            int j   = f / 800;
            int rem = f - j * 800;
            int ch  = rem / 25;
            int tap = rem - ch * 25;
            float wv = conv_w[(size_t)(j * DD + c0 + ch) * 25 + tap] * sinv[j][ch];
            wdup[j][tap][ch] = dup2(wv);
        }
        __syncthreads();

        ull biasr[3];
#pragma unroll
        for (int j = 0; j < 3; j++) biasr[j] = bdup[j][lane5];

        const float* xb = x + (size_t)b * 1024 * DD + c;
        int col0 = slot * 8;

#pragma unroll 1
        for (int gi = 0; gi < 4; gi++) {
            int row = rpair * 4 + gi;

            ull acc[3][4];
#pragma unroll
            for (int j = 0; j < 3; j++)
#pragma unroll
                for (int p = 0; p < 4; p++) acc[j][p] = biasr[j];

#pragma unroll
            for (int dy = 0; dy < 5; dy++) {
                int r = row + dy - 2;
                if ((unsigned)r < 32u) {
                    const float* xr = xb + (size_t)(r * 32) * DD;
                    float xv[12];
#pragma unroll
                    for (int i = 0; i < 12; i++) {
                        int cl = col0 + i - 2;
                        xv[i] = ((unsigned)cl < 32u) ? xr[cl * DD] : 0.f;
                    }
                    ull xp[11];
#pragma unroll
                    for (int i = 0; i < 11; i++) xp[i] = pk2(xv[i], xv[i + 1]);
#pragma unroll
                    for (int j = 0; j < 3; j++) {
#pragma unroll
                        for (int dx = 0; dx < 5; dx++) {
                            ull wd = wdup[j][dy * 5 + dx][lane5];   // LDS.64 broadcast
                            fma2(acc[j][0], wd, xp[dx + 0]);
                            fma2(acc[j][1], wd, xp[dx + 2]);
                            fma2(acc[j][2], wd, xp[dx + 4]);
                            fma2(acc[j][3], wd, xp[dx + 6]);
                        }
                    }
                }
            }

            int head  = c / DH;
            int cc    = c % DH;
            int pix   = ((row >> 4) << 1) + (col0 >> 4);
            int nbase = (row & 15) * 16 + (col0 & 15);
            int obase = (((b * NHEADS + head) * P2 + nbase) * 4 + pix) * DH + cc;
#pragma unroll
            for (int p = 0; p < 4; p++) {
                float2 aq = up2(acc[0][p]);
                float2 ak = up2(acc[1][p]);
                float2 av = up2(acc[2][p]);
                int off0 = obase + (2 * p) * (4 * DH);
                int off1 = off0 + 4 * DH;
                g_Qh[off0] = __float2half_rn(aq.x);
                g_Qh[off1] = __float2half_rn(aq.y);
                g_Kh[off0] = __float2half_rn(ak.x);
                g_Kh[off1] = __float2half_rn(ak.y);
                g_Vh[off0] = __float2half_rn(av.x);
                g_Vh[off1] = __float2half_rn(av.y);
            }
        }
    } else {
        // ================= topk path (R14, 4 warps = 4 windows) ===========
        const unsigned FULL = 0xffffffffu;
        int tkid = bid - min((bid + 5) / 6, 1536);   // 0..8191
        int warp = threadIdx.x >> 5;
        int lane = threadIdx.x & 31;
        int widx = tkid * 4 + warp;                  // 0..32767

        const float* rowp = adj + (size_t)widx * 256;
        unsigned m8[8];
#pragma unroll
        for (int j = 0; j < 8; j++) {
            unsigned u = __float_as_uint(rowp[j * 32 + lane]);
            m8[j] = (u & 0x80000000u) ? ~u : (u | 0x80000000u);
        }

        unsigned bv = m8[0];
        int bj = 0;
#pragma unroll
        for (int j = 1; j < 8; j++)
            if (m8[j] > bv) { bv = m8[j]; bj = j; }

        int mysel = 0;
#pragma unroll 1
        for (int it = 0; it < 8; it++) {
            unsigned wmax = __reduce_max_sync(FULL, bv);
            unsigned bal  = __ballot_sync(FULL, bv == wmax);
            int wl  = __ffs(bal) - 1;
            int bjw = __shfl_sync(FULL, bj, wl);
            if (lane == it) mysel = bjw * 32 + wl;
            if (lane == wl) {                      // only the losing lane rescans
                m8[bj] = 0u;
                bv = m8[0]; bj = 0;
#pragma unroll
                for (int j = 1; j < 8; j++)
                    if (m8[j] > bv) { bv = m8[j]; bj = j; }
            }
        }

        unsigned lo = 0, hi = 0;
#pragma unroll
        for (int it = 0; it < 8; it++) {
            int s = __shfl_sync(FULL, mysel, it) & 255;
            if (it < 4) lo |= (unsigned)s << (8 * it);
            else        hi |= (unsigned)s << (8 * (it - 4));
        }
        if (lane == 0) g_sel[widx] = ((ull)hi << 32) | lo;
    }
}

// ---------------------------------------------------------------------------
// Sparse window attention, tensor-core core (R12), top-k precomputed (R14),
// minBlocksPerSM=8.
// ---------------------------------------------------------------------------
struct WarpSmem {
    float buf[224 * 4];                 // 224 f4: K(half) stage, then V(half); rows 112B
    __align__(16) __half qh[4 * 48];    // q fp16, rows of 96B
};

__global__ __launch_bounds__(128, 8) void attn_kernel(float* __restrict__ out) {
    __shared__ __align__(16) WarpSmem sm[4];
    const unsigned FULL = 0xffffffffu;
    int warp = threadIdx.x >> 5;
    int lane = threadIdx.x & 31;
    int widx = blockIdx.x * 4 + warp;      // 0..32767
    int bh   = widx >> 8;
    int n    = widx & 255;
    int b    = bh >> 4;
    int head = bh & 15;
    WarpSmem& S = sm[warp];

    // ---- stage q (fp16, same [pix][dh] row layout as smem) ----
    {
        const float4* qsrc = (const float4*)(g_Qh + (size_t)widx * 192);
        if (lane < 24) ((float4*)S.qh)[lane] = qsrc[lane];
    }

    // ---- precomputed selections (uniform LDG.64) ----
    ull selu = g_sel[widx];

    // ---- shared fp16 flat-map: 6 insts cover 8 runs x 384B (K and V) ----
    int pack[6];
#pragma unroll
    for (int j = 0; j < 6; j++) {
        int f   = j * 32 + lane;              // f4 index in run space [0,192)
        int run = f / 24;
        int idx = f - run * 24;               // f4 within run
        int pix = idx / 6;
        int c8  = idx - pix * 6;
        int sel = (int)((selu >> (run * 8)) & 255);
        int goff = sel * 24 + idx;
        int slt  = (run * 4 + pix) * 7 + c8;  // rows of 7 f4 (112B)
        pack[j] = (goff << 9) | slt;
    }

    const float4* khg = (const float4*)(g_Kh + (size_t)bh * 49152);
    const float4* vhg = (const float4*)(g_Vh + (size_t)bh * 49152);
    float4* buf4 = (float4*)S.buf;

    // ---- K gather -> smem; V prefetch to regs ----
#pragma unroll
    for (int j = 0; j < 6; j++)
        buf4[pack[j] & 511] = khg[pack[j] >> 9];
    float4 Vp[6];
#pragma unroll
    for (int j = 0; j < 6; j++) Vp[j] = vhg[pack[j] >> 9];
    __syncwarp();

    unsigned bufb = (unsigned)__cvta_generic_to_shared(S.buf);
    unsigned qhb  = (unsigned)__cvta_generic_to_shared(S.qh);
    int t8 = lane >> 3, r8 = lane & 7;

    // ---- K B-fragments: straight ldmatrix (rows = keys, conflict-free) ----
    uint2 kb[3][4];   // [k-chunk][n-tile(keys8)]
#pragma unroll
    for (int c = 0; c < 3; c++)
#pragma unroll
        for (int pr = 0; pr < 2; pr++) {
            int key = (2 * pr + (t8 >> 1)) * 8 + r8;
            unsigned addr = bufb + key * 112 + (16 * c + 8 * (t8 & 1)) * 2;
            uint4 m = ldsm4(addr);
            kb[c][2 * pr]     = make_uint2(m.x, m.y);
            kb[c][2 * pr + 1] = make_uint2(m.z, m.w);
        }

    // ---- Q A-fragments (rows 4-15 alias row 0-3 data; outputs unread) ----
    uint4 qa[3];
    {
        int qr = (t8 & 1) ? 0 : (r8 & 3);
#pragma unroll
        for (int c = 0; c < 3; c++)
            qa[c] = ldsm4(qhb + qr * 96 + (16 * c + (t8 >> 1) * 8) * 2);
    }
    __syncwarp();                          // all K/q smem reads done

    // ---- V -> smem (overwrites K buffer) ----
#pragma unroll
    for (int j = 0; j < 6; j++)
        buf4[pack[j] & 511] = Vp[j];

    // ---- logits: 12 HMMA, fp32 accum ----
    float dl[4][4];
#pragma unroll
    for (int nt = 0; nt < 4; nt++)
#pragma unroll
        for (int i = 0; i < 4; i++) dl[nt][i] = 0.f;
#pragma unroll
    for (int nt = 0; nt < 4; nt++)
#pragma unroll
        for (int c = 0; c < 3; c++)
            mma16816(dl[nt], qa[c], kb[c][nt]);

    // ---- softmax in fragment layout ----
    float mx = -1e30f;
#pragma unroll
    for (int nt = 0; nt < 4; nt++) {
        mx = fmaxf(mx, dl[nt][0]); mx = fmaxf(mx, dl[nt][1]);
    }
    mx = fmaxf(mx, __shfl_xor_sync(FULL, mx, 1));
    mx = fmaxf(mx, __shfl_xor_sync(FULL, mx, 2));
    float e[4][2];
    float s = 0.f;
#pragma unroll
    for (int nt = 0; nt < 4; nt++) {
        e[nt][0] = __expf(dl[nt][0] - mx);
        e[nt][1] = __expf(dl[nt][1] - mx);
        s += e[nt][0] + e[nt][1];
    }
    s += __shfl_xor_sync(FULL, s, 1);
    s += __shfl_xor_sync(FULL, s, 2);
    float inv = __fdividef(1.f, s);

    // ---- A-fragments for A@V: same lane mapping as C-frag, in-register ----
    uint4 af[2];
#pragma unroll
    for (int c = 0; c < 2; c++) {
        __half2 h0 = __floats2half2_rn(e[2 * c][0] * inv,     e[2 * c][1] * inv);
        __half2 h1 = __floats2half2_rn(e[2 * c + 1][0] * inv, e[2 * c + 1][1] * inv);
        af[c] = make_uint4(*(unsigned*)&h0, 0u, *(unsigned*)&h1, 0u);
    }
    __syncwarp();                          // V STS visible

    // ---- V B-fragments: ldmatrix.trans ----
    uint2 vb[6][2];   // [ch-tile][k-chunk(keys16)]
#pragma unroll
    for (int c = 0; c < 2; c++)
#pragma unroll
        for (int pr = 0; pr < 3; pr++) {
            int nt  = 2 * pr + (t8 >> 1);
            int key = 16 * c + 8 * (t8 & 1) + r8;
            unsigned addr = bufb + key * 112 + (8 * nt) * 2;
            uint4 m = ldsm4t(addr);
            vb[2 * pr][c]     = make_uint2(m.x, m.y);
            vb[2 * pr + 1][c] = make_uint2(m.z, m.w);
        }

    // ---- A@V: 12 HMMA ----
    float od[6][4];
#pragma unroll
    for (int nt = 0; nt < 6; nt++)
#pragma unroll
        for (int i = 0; i < 4; i++) od[nt][i] = 0.f;
#pragma unroll
    for (int nt = 0; nt < 6; nt++)
#pragma unroll
        for (int c = 0; c < 2; c++)
            mma16816(od[nt], af[c], vb[nt][c]);

    // ---- store: lanes 0-15 hold rows 0-3 (qp), cols 2(lane%4)+{0,1}+8nt ----
    if (lane < 16) {
        int qp  = lane >> 2;
        int chb = 2 * (lane & 3);
        int wy = n >> 4, wx = n & 15;
        int row = ((qp & 1) << 4) + wy;
        int col = ((qp >> 1) << 4) + wx;
        float* op = out + ((size_t)b * 1024 + row * 32 + col) * 768 + head * 48 + chb;
#pragma unroll
        for (int nt = 0; nt < 6; nt++)
            *(float2*)(op + 8 * nt) = make_float2(od[nt][0], od[nt][1]);
    }
}

// ---------------------------------------------------------------------------
extern "C" void kernel_launch(void* const* d_in, const int* in_sizes, int n_in,
                              void* d_out, int out_size) {
    const float* x      = (const float*)d_in[0];
    // d_in[1] = noise (unused by reference)
    const float* adj    = (const float*)d_in[2];
    const float* conv_w = (const float*)d_in[3];
    const float* gamma  = (const float*)d_in[4];
    const float* beta   = (const float*)d_in[5];
    const float* mean   = (const float*)d_in[6];
    const float* var    = (const float*)d_in[7];
    // d_in[8] = sparsity (constant 8, compiled in)
    float* out = (float*)d_out;

    convtopk_kernel<<<9728, 128>>>(x, conv_w, gamma, beta, mean, var, adj);
    attn_kernel<<<8192, 128>>>(out);
}

// round 17
// speedup vs baseline: 1.2785x; 1.2785x over previous
#include <cuda_runtime.h>
#include <cuda_fp16.h>
#include <math.h>

#define BB 8
#define NHEADS 16
#define DH 48
#define DD 768
#define P2 256

typedef unsigned long long ull;

// ---- f32x2 packed helpers ----
__device__ __forceinline__ ull pk2(float lo, float hi) {
    ull r; asm("mov.b64 %0,{%1,%2};" : "=l"(r) : "f"(lo), "f"(hi)); return r;
}
__device__ __forceinline__ void fma2(ull& d, ull a, ull b) {
    asm("fma.rn.f32x2 %0,%1,%2,%0;" : "+l"(d) : "l"(a), "l"(b));
}
__device__ __forceinline__ float2 up2(ull v) {
    float2 r; asm("mov.b64 {%0,%1},%2;" : "=f"(r.x), "=f"(r.y) : "l"(v)); return r;
}

// ---- tensor-core helpers ----
__device__ __forceinline__ uint4 ldsm4(unsigned a) {
    uint4 r;
    asm volatile("ldmatrix.sync.aligned.m8n8.x4.shared.b16 {%0,%1,%2,%3},[%4];"
                 : "=r"(r.x), "=r"(r.y), "=r"(r.z), "=r"(r.w) : "r"(a));
    return r;
}
__device__ __forceinline__ uint4 ldsm4t(unsigned a) {
    uint4 r;
    asm volatile("ldmatrix.sync.aligned.m8n8.x4.trans.shared.b16 {%0,%1,%2,%3},[%4];"
                 : "=r"(r.x), "=r"(r.y), "=r"(r.z), "=r"(r.w) : "r"(a));
    return r;
}
__device__ __forceinline__ void mma16816(float d[4], const uint4& a, const uint2& b) {
    asm volatile("mma.sync.aligned.m16n8k16.row.col.f32.f16.f16.f32 "
                 "{%0,%1,%2,%3},{%4,%5,%6,%7},{%8,%9},{%0,%1,%2,%3};"
                 : "+f"(d[0]), "+f"(d[1]), "+f"(d[2]), "+f"(d[3])
                 : "r"(a.x), "r"(a.y), "r"(a.z), "r"(a.w), "r"(b.x), "r"(b.y));
}

// Scratch: windowified Q/K/V all fp16  [b][head][n][pix4][dh], 128B aligned
__device__ __align__(128) __half g_Qh[BB*NHEADS*P2*4*DH];
__device__ __align__(128) __half g_Kh[BB*NHEADS*P2*4*DH];
__device__ __align__(128) __half g_Vh[BB*NHEADS*P2*4*DH];

// ---------------------------------------------------------------------------
// Fused BN-fold + depthwise 5x5 conv for q,k,v (q pre-scaled by d^-0.5).
// CHANNEL-PAIR f32x2 packing: thread = (channel-pair cp, col-group cg of 4).
// x loads are LDG.64 of adjacent channels (pre-packed, zero pk2 movs),
// weights are per-pair ull in smem (1 wavefront per LDS), stores are half2.
// Block: 128 thr = 16 cp x 8 cg (32 ch x 32 cols), 4 rows sequentially.
// Grid: (24 chunks * 8 rowbands, 8 b).
// ---------------------------------------------------------------------------
__global__ __launch_bounds__(128) void conv_kernel(const float* __restrict__ x,
                                                   const float* __restrict__ conv_w,
                                                   const float* __restrict__ gamma,
                                                   const float* __restrict__ beta,
                                                   const float* __restrict__ mean,
                                                   const float* __restrict__ var) {
    __shared__ ull   wpair[3][25][16];   // (w[2cp], w[2cp+1]) folded
    __shared__ ull   bpair[3][16];
    __shared__ float sinv[3][32];
    __shared__ float sbias[3][32];

    int tid   = threadIdx.x;
    int b     = blockIdx.y;
    int chunk = blockIdx.x >> 3;
    int rpair = blockIdx.x & 7;       // 4-row band
    int cp    = tid & 15;             // channel pair within chunk
    int cg    = tid >> 4;             // 0..7 -> cols cg*4..cg*4+3
    int c0    = chunk * 32;

    // ---- fold BN ----
    if (tid < 96) {
        int j  = tid / 32;
        int cl = tid % 32;
        int t  = j * DD + c0 + cl;
        float inv = gamma[t] * rsqrtf(var[t] + 1e-5f);
        float bs  = beta[t] - mean[t] * inv;
        if (j == 0) { inv *= 0.03608439182435161f; bs *= 0.03608439182435161f; } // 768^-0.5
        sinv[j][cl]  = inv;
        sbias[j][cl] = bs;
    }
    __syncthreads();

    // ---- stage folded per-pair weights ----
    for (int f = tid; f < 3 * 25 * 16; f += 128) {
        int j   = f / 400;
        int rem = f - j * 400;
        int tap = rem >> 4;
        int cpp = rem & 15;
        float w0 = conv_w[(size_t)(j * DD + c0 + 2 * cpp)     * 25 + tap] * sinv[j][2 * cpp];
        float w1 = conv_w[(size_t)(j * DD + c0 + 2 * cpp + 1) * 25 + tap] * sinv[j][2 * cpp + 1];
        wpair[j][tap][cpp] = pk2(w0, w1);
    }
    if (tid < 48) {
        int j = tid / 16, cpp = tid & 15;
        bpair[j][cpp] = pk2(sbias[j][2 * cpp], sbias[j][2 * cpp + 1]);
    }
    __syncthreads();

    ull biasr[3];
#pragma unroll
    for (int j = 0; j < 3; j++) biasr[j] = bpair[j][cp];

    const float* xb = x + (size_t)b * 1024 * DD + c0 + 2 * cp;
    int col0 = cg * 4;
    int cch  = c0 + 2 * cp;
    int head = cch / DH;
    int cc   = cch % DH;

#pragma unroll 1
    for (int gi = 0; gi < 4; gi++) {
        int row = rpair * 4 + gi;

        ull acc[3][4];
#pragma unroll
        for (int j = 0; j < 3; j++)
#pragma unroll
            for (int i = 0; i < 4; i++) acc[j][i] = biasr[j];

#pragma unroll
        for (int dy = 0; dy < 5; dy++) {
            int r = row + dy - 2;
            if ((unsigned)r < 32u) {
                const float* xr = xb + (size_t)(r * 32) * DD;
                ull xp[8];
#pragma unroll
                for (int i = 0; i < 8; i++) {
                    int cl = col0 + i - 2;
                    xp[i] = ((unsigned)cl < 32u) ? *(const ull*)(xr + (size_t)cl * DD) : 0ull;
                }
#pragma unroll
                for (int j = 0; j < 3; j++) {
#pragma unroll
                    for (int dx = 0; dx < 5; dx++) {
                        ull wd = wpair[j][dy * 5 + dx][cp];   // LDS.64, 1 wavefront
                        fma2(acc[j][0], wd, xp[dx + 0]);
                        fma2(acc[j][1], wd, xp[dx + 1]);
                        fma2(acc[j][2], wd, xp[dx + 2]);
                        fma2(acc[j][3], wd, xp[dx + 3]);
                    }
                }
            }
        }

        int pix   = ((row >> 4) << 1) + (col0 >> 4);
        int nbase = (row & 15) * 16 + (col0 & 15);
        int obase = (((b * NHEADS + head) * P2 + nbase) * 4 + pix) * DH + cc;
#pragma unroll
        for (int i = 0; i < 4; i++) {
            float2 aq = up2(acc[0][i]);
            float2 ak = up2(acc[1][i]);
            float2 av = up2(acc[2][i]);
            int off = obase + i * (4 * DH);   // n increments by 1 per col
            *(__half2*)(g_Qh + off) = __floats2half2_rn(aq.x, aq.y);
            *(__half2*)(g_Kh + off) = __floats2half2_rn(ak.x, ak.y);
            *(__half2*)(g_Vh + off) = __floats2half2_rn(av.x, av.y);
        }
    }
}

// ---------------------------------------------------------------------------
// Fused top-8 + sparse window attention, tensor-core core, minBlocks=8.
// (R15 verbatim — best measured attn at 45.8us)
// ---------------------------------------------------------------------------
struct WarpSmem {
    float buf[224 * 4];                 // 224 f4: K(half) stage, then V(half); rows 112B
    __align__(16) __half qh[4 * 48];    // q fp16, rows of 96B
};

__global__ __launch_bounds__(128, 8) void attn_kernel(const float* __restrict__ adj,
                                                      float* __restrict__ out) {
    __shared__ __align__(16) WarpSmem sm[4];
    const unsigned FULL = 0xffffffffu;
    int warp = threadIdx.x >> 5;
    int lane = threadIdx.x & 31;
    int widx = blockIdx.x * 4 + warp;      // 0..32767
    int bh   = widx >> 8;
    int n    = widx & 255;
    int b    = bh >> 4;
    int head = bh & 15;
    WarpSmem& S = sm[warp];

    // ---- stage q (fp16, same [pix][dh] row layout as smem) ----
    {
        const float4* qsrc = (const float4*)(g_Qh + (size_t)widx * 192);
        if (lane < 24) ((float4*)S.qh)[lane] = qsrc[lane];
    }

    // ---- top-8: incremental monotone-uint REDUX argmax ----
    const float* rowp = adj + ((size_t)bh * 256 + n) * 256;
    unsigned m8[8];
#pragma unroll
    for (int j = 0; j < 8; j++) {
        unsigned u = __float_as_uint(rowp[j * 32 + lane]);
        m8[j] = (u & 0x80000000u) ? ~u : (u | 0x80000000u);
    }

    unsigned bv = m8[0];
    int bj = 0;
#pragma unroll
    for (int j = 1; j < 8; j++)
        if (m8[j] > bv) { bv = m8[j]; bj = j; }

    int mysel = 0;
#pragma unroll 1
    for (int it = 0; it < 8; it++) {
        unsigned wmax = __reduce_max_sync(FULL, bv);
        unsigned bal  = __ballot_sync(FULL, bv == wmax);
        int wl  = __ffs(bal) - 1;
        int bjw = __shfl_sync(FULL, bj, wl);
        if (lane == it) mysel = bjw * 32 + wl;
        if (lane == wl) {
            m8[bj] = 0u;
            bv = m8[0]; bj = 0;
#pragma unroll
            for (int j = 1; j < 8; j++)
                if (m8[j] > bv) { bv = m8[j]; bj = j; }
        }
    }

    // ---- shared fp16 flat-map: 6 insts cover 8 runs x 384B (K and V) ----
    int pack[6];
#pragma unroll
    for (int j = 0; j < 6; j++) {
        int f   = j * 32 + lane;              // f4 index in run space [0,192)
        int run = f / 24;
        int idx = f - run * 24;               // f4 within run
        int pix = idx / 6;
        int c8  = idx - pix * 6;
        int sel = __shfl_sync(FULL, mysel, run);
        int goff = sel * 24 + idx;
        int slt  = (run * 4 + pix) * 7 + c8;  // rows of 7 f4 (112B)
        pack[j] = (goff << 9) | slt;
    }

    const float4* khg = (const float4*)(g_Kh + (size_t)bh * 49152);
    const float4* vhg = (const float4*)(g_Vh + (size_t)bh * 49152);
    float4* buf4 = (float4*)S.buf;

    // ---- K gather -> smem; V prefetch to regs ----
#pragma unroll
    for (int j = 0; j < 6; j++)
        buf4[pack[j] & 511] = khg[pack[j] >> 9];
    float4 Vp[6];
#pragma unroll
    for (int j = 0; j < 6; j++) Vp[j] = vhg[pack[j] >> 9];
    __syncwarp();

    unsigned bufb = (unsigned)__cvta_generic_to_shared(S.buf);
    unsigned qhb  = (unsigned)__cvta_generic_to_shared(S.qh);
    int t8 = lane >> 3, r8 = lane & 7;

    // ---- K B-fragments: straight ldmatrix (rows = keys, conflict-free) ----
    uint2 kb[3][4];   // [k-chunk][n-tile(keys8)]
#pragma unroll
    for (int c = 0; c < 3; c++)
#pragma unroll
        for (int pr = 0; pr < 2; pr++) {
            int key = (2 * pr + (t8 >> 1)) * 8 + r8;
            unsigned addr = bufb + key * 112 + (16 * c + 8 * (t8 & 1)) * 2;
            uint4 m = ldsm4(addr);
            kb[c][2 * pr]     = make_uint2(m.x, m.y);
            kb[c][2 * pr + 1] = make_uint2(m.z, m.w);
        }

    // ---- Q A-fragments (rows 4-15 alias row 0-3 data; outputs unread) ----
    uint4 qa[3];
    {
        int qr = (t8 & 1) ? 0 : (r8 & 3);
#pragma unroll
        for (int c = 0; c < 3; c++)
            qa[c] = ldsm4(qhb + qr * 96 + (16 * c + (t8 >> 1) * 8) * 2);
    }
    __syncwarp();                          // all K/q smem reads done

    // ---- V -> smem (overwrites K buffer) ----
#pragma unroll
    for (int j = 0; j < 6; j++)
        buf4[pack[j] & 511] = Vp[j];

    // ---- logits: 12 HMMA, fp32 accum ----
    float dl[4][4];
#pragma unroll
    for (int nt = 0; nt < 4; nt++)
#pragma unroll
        for (int i = 0; i < 4; i++) dl[nt][i] = 0.f;
#pragma unroll
    for (int nt = 0; nt < 4; nt++)
#pragma unroll
        for (int c = 0; c < 3; c++)
            mma16816(dl[nt], qa[c], kb[c][nt]);

    // ---- softmax in fragment layout ----
    float mx = -1e30f;
#pragma unroll
    for (int nt = 0; nt < 4; nt++) {
        mx = fmaxf(mx, dl[nt][0]); mx = fmaxf(mx, dl[nt][1]);
    }
    mx = fmaxf(mx, __shfl_xor_sync(FULL, mx, 1));
    mx = fmaxf(mx, __shfl_xor_sync(FULL, mx, 2));
    float e[4][2];
    float s = 0.f;
#pragma unroll
    for (int nt = 0; nt < 4; nt++) {
        e[nt][0] = __expf(dl[nt][0] - mx);
        e[nt][1] = __expf(dl[nt][1] - mx);
        s += e[nt][0] + e[nt][1];
    }
    s += __shfl_xor_sync(FULL, s, 1);
    s += __shfl_xor_sync(FULL, s, 2);
    float inv = __fdividef(1.f, s);

    // ---- A-fragments for A@V: same lane mapping as C-frag, in-register ----
    uint4 af[2];
#pragma unroll
    for (int c = 0; c < 2; c++) {
        __half2 h0 = __floats2half2_rn(e[2 * c][0] * inv,     e[2 * c][1] * inv);
        __half2 h1 = __floats2half2_rn(e[2 * c + 1][0] * inv, e[2 * c + 1][1] * inv);
        af[c] = make_uint4(*(unsigned*)&h0, 0u, *(unsigned*)&h1, 0u);
    }
    __syncwarp();                          // V STS visible

    // ---- V B-fragments: ldmatrix.trans ----
    uint2 vb[6][2];   // [ch-tile][k-chunk(keys16)]
#pragma unroll
    for (int c = 0; c < 2; c++)
#pragma unroll
        for (int pr = 0; pr < 3; pr++) {
            int nt  = 2 * pr + (t8 >> 1);
            int key = 16 * c + 8 * (t8 & 1) + r8;
            unsigned addr = bufb + key * 112 + (8 * nt) * 2;
            uint4 m = ldsm4t(addr);
            vb[2 * pr][c]     = make_uint2(m.x, m.y);
            vb[2 * pr + 1][c] = make_uint2(m.z, m.w);
        }

    // ---- A@V: 12 HMMA ----
    float od[6][4];
#pragma unroll
    for (int nt = 0; nt < 6; nt++)
#pragma unroll
        for (int i = 0; i < 4; i++) od[nt][i] = 0.f;
#pragma unroll
    for (int nt = 0; nt < 6; nt++)
#pragma unroll
        for (int c = 0; c < 2; c++)
            mma16816(od[nt], af[c], vb[nt][c]);

    // ---- store: lanes 0-15 hold rows 0-3 (qp), cols 2(lane%4)+{0,1}+8nt ----
    if (lane < 16) {
        int qp  = lane >> 2;
        int chb = 2 * (lane & 3);
        int wy = n >> 4, wx = n & 15;
        int row = ((qp & 1) << 4) + wy;
        int col = ((qp >> 1) << 4) + wx;
        float* op = out + ((size_t)b * 1024 + row * 32 + col) * 768 + head * 48 + chb;
#pragma unroll
        for (int nt = 0; nt < 6; nt++)
            *(float2*)(op + 8 * nt) = make_float2(od[nt][0], od[nt][1]);
    }
}

// ---------------------------------------------------------------------------
extern "C" void kernel_launch(void* const* d_in, const int* in_sizes, int n_in,
                              void* d_out, int out_size) {
    const float* x      = (const float*)d_in[0];
    // d_in[1] = noise (unused by reference)
    const float* adj    = (const float*)d_in[2];
    const float* conv_w = (const float*)d_in[3];
    const float* gamma  = (const float*)d_in[4];
    const float* beta   = (const float*)d_in[5];
    const float* mean   = (const float*)d_in[6];
    const float* var    = (const float*)d_in[7];
    // d_in[8] = sparsity (constant 8, compiled in)
    float* out = (float*)d_out;

    conv_kernel<<<dim3(192, 8), 128>>>(x, conv_w, gamma, beta, mean, var);
    attn_kernel<<<8192, 128>>>(adj, out);
}